// round 1
// baseline (speedup 1.0000x reference)
#include <cuda_runtime.h>
#include <cuda_bf16.h>

#define N_NODES 100000
#define N_EDGES 1600000
#define F_IN 128
#define N_H 3
#define N_D 16
#define HD 48
#define NEG_SLOPE 0.2f

// Scratch (device globals: no allocation allowed in kernel_launch)
__device__ float  g_feat[N_NODES * HD];   // projected features, (N,48)
__device__ float4 g_el[N_NODES];          // (el0,el1,el2,_)
__device__ float4 g_er[N_NODES];          // (er0,er1,er2,_)
__device__ float4 g_ex[N_EDGES];          // per-edge exp(e), (x0,x1,x2,_)
__device__ float4 g_denom[N_NODES];       // softmax denominators per head

__device__ __forceinline__ void red_add_v4(float4* p, float a, float b, float c, float d) {
    asm volatile("red.global.add.v4.f32 [%0], {%1, %2, %3, %4};"
                 :: "l"(p), "f"(a), "f"(b), "f"(c), "f"(d) : "memory");
}

// ---------------------------------------------------------------------------
// Kernel 0: zero msg accumulator (d_out) and denominators
// ---------------------------------------------------------------------------
__global__ void k_init(float* __restrict__ out) {
    int i = blockIdx.x * blockDim.x + threadIdx.x;
    if (i < N_NODES * HD) out[i] = 0.0f;
    if (i < N_NODES) g_denom[i] = make_float4(0.f, 0.f, 0.f, 0.f);
}

// ---------------------------------------------------------------------------
// Kernel 1: feat = x @ W^T  (N x 48), plus el/er attention logits.
// 128 threads/block, 2 nodes per thread (amortize the W broadcast LDS).
// W staged transposed in SMEM: Ws[k][j] = W[j*128 + k].
// ---------------------------------------------------------------------------
__global__ __launch_bounds__(128) void k_gemm(const float* __restrict__ x,
                                              const float* __restrict__ W,
                                              const float* __restrict__ al,
                                              const float* __restrict__ ar)
{
    __shared__ float Ws[F_IN][HD];
    __shared__ float als[HD], ars[HD];
    for (int i = threadIdx.x; i < HD * F_IN; i += 128) {
        int j = i / F_IN, k = i % F_IN;
        Ws[k][j] = W[i];
    }
    if (threadIdx.x < HD) {
        als[threadIdx.x] = al[threadIdx.x];
        ars[threadIdx.x] = ar[threadIdx.x];
    }
    __syncthreads();

    int t  = blockIdx.x * 128 + threadIdx.x;
    int n0 = 2 * t, n1 = 2 * t + 1;
    if (n0 >= N_NODES) return;
    bool has1 = (n1 < N_NODES);

    float acc0[HD], acc1[HD];
#pragma unroll
    for (int j = 0; j < HD; j++) { acc0[j] = 0.f; acc1[j] = 0.f; }

    const float4* x4 = (const float4*)x;
    int b0 = n0 * (F_IN / 4);
    int b1 = n1 * (F_IN / 4);

    for (int i = 0; i < F_IN / 4; i++) {
        float4 a = x4[b0 + i];
        float4 b = has1 ? x4[b1 + i] : make_float4(0.f, 0.f, 0.f, 0.f);
#pragma unroll
        for (int j = 0; j < HD; j++) {
            float w0 = Ws[4 * i + 0][j];
            float w1 = Ws[4 * i + 1][j];
            float w2 = Ws[4 * i + 2][j];
            float w3 = Ws[4 * i + 3][j];
            acc0[j] = fmaf(a.x, w0, fmaf(a.y, w1, fmaf(a.z, w2, fmaf(a.w, w3, acc0[j]))));
            acc1[j] = fmaf(b.x, w0, fmaf(b.y, w1, fmaf(b.z, w2, fmaf(b.w, w3, acc1[j]))));
        }
    }

    // node n0: logits + feature store
    {
        float el[N_H], er[N_H];
#pragma unroll
        for (int h = 0; h < N_H; h++) { el[h] = 0.f; er[h] = 0.f; }
#pragma unroll
        for (int h = 0; h < N_H; h++)
#pragma unroll
            for (int d = 0; d < N_D; d++) {
                el[h] = fmaf(acc0[h * N_D + d], als[h * N_D + d], el[h]);
                er[h] = fmaf(acc0[h * N_D + d], ars[h * N_D + d], er[h]);
            }
        g_el[n0] = make_float4(el[0], el[1], el[2], 0.f);
        g_er[n0] = make_float4(er[0], er[1], er[2], 0.f);
        float4* f4 = (float4*)(g_feat + (size_t)n0 * HD);
#pragma unroll
        for (int j = 0; j < HD / 4; j++)
            f4[j] = make_float4(acc0[4 * j], acc0[4 * j + 1], acc0[4 * j + 2], acc0[4 * j + 3]);
    }
    if (has1) {
        float el[N_H], er[N_H];
#pragma unroll
        for (int h = 0; h < N_H; h++) { el[h] = 0.f; er[h] = 0.f; }
#pragma unroll
        for (int h = 0; h < N_H; h++)
#pragma unroll
            for (int d = 0; d < N_D; d++) {
                el[h] = fmaf(acc1[h * N_D + d], als[h * N_D + d], el[h]);
                er[h] = fmaf(acc1[h * N_D + d], ars[h * N_D + d], er[h]);
            }
        g_el[n1] = make_float4(el[0], el[1], el[2], 0.f);
        g_er[n1] = make_float4(er[0], er[1], er[2], 0.f);
        float4* f4 = (float4*)(g_feat + (size_t)n1 * HD);
#pragma unroll
        for (int j = 0; j < HD / 4; j++)
            f4[j] = make_float4(acc1[4 * j], acc1[4 * j + 1], acc1[4 * j + 2], acc1[4 * j + 3]);
    }
}

// ---------------------------------------------------------------------------
// Kernel 2: per-edge attention logit -> exp, accumulate softmax denominator.
// Max-subtraction is skipped: |e| <= ~4 here, softmax is shift-invariant.
// ---------------------------------------------------------------------------
__global__ void k_edge_attn(const int* __restrict__ src, const int* __restrict__ dst) {
    int e = blockIdx.x * blockDim.x + threadIdx.x;
    if (e >= N_EDGES) return;
    int s = src[e], d = dst[e];
    float4 L = g_el[s];
    float4 R = g_er[d];
    float v0 = L.x + R.x, v1 = L.y + R.y, v2 = L.z + R.z;
    v0 = v0 > 0.f ? v0 : NEG_SLOPE * v0;
    v1 = v1 > 0.f ? v1 : NEG_SLOPE * v1;
    v2 = v2 > 0.f ? v2 : NEG_SLOPE * v2;
    float x0 = __expf(v0), x1 = __expf(v1), x2 = __expf(v2);
    g_ex[e] = make_float4(x0, x1, x2, 0.f);
    red_add_v4(&g_denom[d], x0, x1, x2, 0.f);
}

// ---------------------------------------------------------------------------
// Kernel 3: per-edge weighted feature aggregation into d_out (msg buffer).
// ---------------------------------------------------------------------------
__global__ void k_edge_agg(const int* __restrict__ src, const int* __restrict__ dst,
                           float* __restrict__ out) {
    int e = blockIdx.x * blockDim.x + threadIdx.x;
    if (e >= N_EDGES) return;
    int s = src[e], d = dst[e];
    float4 X  = g_ex[e];
    float4 Dn = g_denom[d];
    float a0 = X.x / Dn.x;
    float a1 = X.y / Dn.y;
    float a2 = X.z / Dn.z;
    const float4* fs = (const float4*)(g_feat + (size_t)s * HD);
    float4* od = (float4*)(out + (size_t)d * HD);
#pragma unroll
    for (int j = 0; j < HD / 4; j++) {
        float a = (j < 4) ? a0 : ((j < 8) ? a1 : a2);
        float4 f = fs[j];
        red_add_v4(&od[j], a * f.x, a * f.y, a * f.z, a * f.w);
    }
}

// ---------------------------------------------------------------------------
// Kernel 4: out = (1-lin)*msg + lin*feat
// ---------------------------------------------------------------------------
__global__ void k_final(const float* __restrict__ lin, float* __restrict__ out) {
    int i = blockIdx.x * blockDim.x + threadIdx.x;  // over N*12 float4s
    if (i >= N_NODES * (HD / 4)) return;
    float l = lin[i / (HD / 4)];
    float4 m = ((const float4*)out)[i];
    float4 f = ((const float4*)g_feat)[i];
    float4 r;
    r.x = (1.f - l) * m.x + l * f.x;
    r.y = (1.f - l) * m.y + l * f.y;
    r.z = (1.f - l) * m.z + l * f.z;
    r.w = (1.f - l) * m.w + l * f.w;
    ((float4*)out)[i] = r;
}

// ---------------------------------------------------------------------------
extern "C" void kernel_launch(void* const* d_in, const int* in_sizes, int n_in,
                              void* d_out, int out_size) {
    const float* x   = (const float*)d_in[0];
    const float* W   = (const float*)d_in[1];
    const float* al  = (const float*)d_in[2];
    const float* ar  = (const float*)d_in[3];
    const float* lin = (const float*)d_in[4];
    const int*   src = (const int*)d_in[5];
    const int*   dst = (const int*)d_in[6];
    float* out = (float*)d_out;

    k_init<<<(N_NODES * HD + 255) / 256, 256>>>(out);
    k_gemm<<<(N_NODES + 255) / 256, 128>>>(x, W, al, ar);
    k_edge_attn<<<(N_EDGES + 255) / 256, 256>>>(src, dst);
    k_edge_agg<<<(N_EDGES + 255) / 256, 256>>>(src, dst, out);
    k_final<<<(N_NODES * (HD / 4) + 255) / 256, 256>>>(lin, out);
}